// round 6
// baseline (speedup 1.0000x reference)
#include <cuda_runtime.h>
#include <math.h>

#define NN   100000
#define EE   3200000
#define INC  128
#define HIDC 16
#define SCAN_B 1024
#define NBLK ((NN + SCAN_B - 1) / SCAN_B)   // 98

// ---------------- scratch ----------------
__device__ int   g_degi[NN];
__device__ float g_dinv[NN];
__device__ int   g_start[NN + 1];
__device__ int   g_cur[NN];
__device__ int   g_bsum[128];
__device__ int   g_csr[EE];                  // src only (features pre-scaled)
__device__ float g_h1[(long long)NN * HIDC]; // h1 * dinv[node]
__device__ float g_h2[NN];                   // h2 * dinv[node]
__device__ int   g_is64;

// ---------------- edge dtype auto-detect ----------------
__global__ void detect_kernel(const void* ei) {
    __shared__ int bad;
    if (threadIdx.x == 0) bad = 0;
    __syncthreads();
    const long long* p = (const long long*)ei;
    long long v = p[threadIdx.x];
    if (v < 0 || v >= NN) bad = 1;
    __syncthreads();
    if (threadIdx.x == 0) g_is64 = bad ? 0 : 1;
}

// ---------------- degree (reads dst half only) ----------------
__global__ void degree_kernel(const void* ei) {
    long long e = (long long)blockIdx.x * blockDim.x + threadIdx.x;
    if (e >= EE) return;
    int d;
    if (g_is64) {
        const long long* p = (const long long*)ei;
        d = (int)p[(long long)EE + e];
    } else {
        const int* p = (const int*)ei;
        d = p[(long long)EE + e];
    }
    atomicAdd(&g_degi[d], 1);
}

// ---------------- prefix scan (dinv fused into scan1) ----------------
__global__ void scan1_kernel() {
    __shared__ int sh[SCAN_B];
    int t = threadIdx.x;
    int i = blockIdx.x * SCAN_B + t;
    int v = (i < NN) ? g_degi[i] : 0;
    if (i < NN) g_dinv[i] = rsqrtf((float)v + 1.0f);
    sh[t] = v;
#pragma unroll
    for (int off = 1; off < SCAN_B; off <<= 1) {
        __syncthreads();
        int add = (t >= off) ? sh[t - off] : 0;
        __syncthreads();
        sh[t] += add;
    }
    __syncthreads();
    if (i < NN) g_start[i] = sh[t] - v;
    if (t == SCAN_B - 1) g_bsum[blockIdx.x] = sh[t];
}

__global__ void scan2_kernel() {
    __shared__ int sh[128];
    int t = threadIdx.x;
    int v = (t < NBLK) ? g_bsum[t] : 0;
    sh[t] = v;
#pragma unroll
    for (int off = 1; off < 128; off <<= 1) {
        __syncthreads();
        int add = (t >= off) ? sh[t - off] : 0;
        __syncthreads();
        sh[t] += add;
    }
    __syncthreads();
    if (t < NBLK) g_bsum[t] = sh[t] - v;
}

__global__ void scan3_kernel() {
    int i = blockIdx.x * blockDim.x + threadIdx.x;
    if (i >= NN) return;
    int s = g_start[i] + g_bsum[i >> 10];
    g_start[i] = s;
    g_cur[i] = s;
    if (i == 0) g_start[NN] = EE;
}

// ---------------- scatter: CSR of src only (reads edge index directly) ----------------
__global__ void scatter_kernel(const void* ei) {
    long long e = (long long)blockIdx.x * blockDim.x + threadIdx.x;
    if (e >= EE) return;
    int s, d;
    if (g_is64) {
        const long long* p = (const long long*)ei;
        s = (int)p[e];
        d = (int)p[(long long)EE + e];
    } else {
        const int* p = (const int*)ei;
        s = p[e];
        d = p[(long long)EE + e];
    }
    int pos = atomicAdd(&g_cur[d], 1);
    g_csr[pos] = s;
}

// ---------------- h1 = (x @ W1) * dinv[node] ----------------
__global__ void __launch_bounds__(256) gemm1_kernel(const float* __restrict__ x,
                                                    const float* __restrict__ W1) {
    __shared__ float sW[INC * HIDC];
    __shared__ float sx[64 * 68];
    int t = threadIdx.x;
    long long base = (long long)blockIdx.x * 64;
    int local = t >> 2;
    int cg    = (t & 3) * 4;

    for (int i = t; i < INC * HIDC; i += 256) sW[i] = W1[i];

    float a0 = 0.f, a1 = 0.f, a2 = 0.f, a3 = 0.f;

#pragma unroll
    for (int kt = 0; kt < 2; kt++) {
        __syncthreads();
        const float4* x4 = (const float4*)x;
        for (int j = t; j < 1024; j += 256) {
            int r = j >> 4, c4 = j & 15;
            long long node = base + r;
            float4 v = (node < NN) ? x4[node * 32 + kt * 16 + c4]
                                   : make_float4(0.f, 0.f, 0.f, 0.f);
            *(float4*)&sx[r * 68 + c4 * 4] = v;
        }
        __syncthreads();
        const float* xr = &sx[local * 68];
        const float* wb = &sW[kt * 64 * HIDC + cg];
#pragma unroll 8
        for (int k = 0; k < 64; k++) {
            float xv = xr[k];
            float4 w = *(const float4*)(wb + k * HIDC);
            a0 = fmaf(xv, w.x, a0);
            a1 = fmaf(xv, w.y, a1);
            a2 = fmaf(xv, w.z, a2);
            a3 = fmaf(xv, w.w, a3);
        }
    }
    long long node = base + local;
    if (node < NN) {
        float di = g_dinv[node];
        *(float4*)&g_h1[node * HIDC + cg] =
            make_float4(a0 * di, a1 * di, a2 * di, a3 * di);
    }
}

// ---------------- layer-1 gather + self-loop + bias + relu + W2 dot ----------------
// 4 threads/node, 4 channels each; edge loop unrolled x8 for MLP.
__global__ void __launch_bounds__(256) agg1_fused_kernel(const float* __restrict__ b1,
                                                         const float* __restrict__ W2) {
    long long idx = (long long)blockIdx.x * blockDim.x + threadIdx.x;
    long long node = idx >> 2;
    if (node >= NN) return;
    int cg = (int)(idx & 3) * 4;

    int beg = g_start[node];
    int end = g_start[node + 1];
    float a0 = 0.f, a1 = 0.f, a2 = 0.f, a3 = 0.f;
    int e = beg;
    for (; e + 8 <= end; e += 8) {
        int s0 = __ldg(&g_csr[e]);
        int s1 = __ldg(&g_csr[e + 1]);
        int s2 = __ldg(&g_csr[e + 2]);
        int s3 = __ldg(&g_csr[e + 3]);
        int s4 = __ldg(&g_csr[e + 4]);
        int s5 = __ldg(&g_csr[e + 5]);
        int s6 = __ldg(&g_csr[e + 6]);
        int s7 = __ldg(&g_csr[e + 7]);
        float4 h0 = *(const float4*)&g_h1[(long long)s0 * HIDC + cg];
        float4 h1 = *(const float4*)&g_h1[(long long)s1 * HIDC + cg];
        float4 h2 = *(const float4*)&g_h1[(long long)s2 * HIDC + cg];
        float4 h3 = *(const float4*)&g_h1[(long long)s3 * HIDC + cg];
        float4 h4 = *(const float4*)&g_h1[(long long)s4 * HIDC + cg];
        float4 h5 = *(const float4*)&g_h1[(long long)s5 * HIDC + cg];
        float4 h6 = *(const float4*)&g_h1[(long long)s6 * HIDC + cg];
        float4 h7 = *(const float4*)&g_h1[(long long)s7 * HIDC + cg];
        a0 += (h0.x + h1.x) + (h2.x + h3.x) + ((h4.x + h5.x) + (h6.x + h7.x));
        a1 += (h0.y + h1.y) + (h2.y + h3.y) + ((h4.y + h5.y) + (h6.y + h7.y));
        a2 += (h0.z + h1.z) + (h2.z + h3.z) + ((h4.z + h5.z) + (h6.z + h7.z));
        a3 += (h0.w + h1.w) + (h2.w + h3.w) + ((h4.w + h5.w) + (h6.w + h7.w));
    }
    for (; e < end; e++) {
        int s = __ldg(&g_csr[e]);
        float4 h = *(const float4*)&g_h1[(long long)s * HIDC + cg];
        a0 += h.x; a1 += h.y; a2 += h.z; a3 += h.w;
    }
    float4 hs = *(const float4*)&g_h1[node * HIDC + cg];
    float di = g_dinv[node];
    float4 bb = *(const float4*)&b1[cg];
    float4 w2 = *(const float4*)&W2[cg];
    float v = fmaxf(fmaf(a0 + hs.x, di, bb.x), 0.f) * w2.x
            + fmaxf(fmaf(a1 + hs.y, di, bb.y), 0.f) * w2.y
            + fmaxf(fmaf(a2 + hs.z, di, bb.z), 0.f) * w2.z
            + fmaxf(fmaf(a3 + hs.w, di, bb.w), 0.f) * w2.w;
    v += __shfl_down_sync(0xffffffffu, v, 2, 4);
    v += __shfl_down_sync(0xffffffffu, v, 1, 4);
    if ((idx & 3) == 0) g_h2[node] = v * di;   // pre-scale for layer 2
}

// ---------------- layer-2 gather + self-loop + bias + sigmoid ----------------
__global__ void __launch_bounds__(256) agg2_final_kernel(const float* __restrict__ b2,
                                                         float* __restrict__ out) {
    long long idx = (long long)blockIdx.x * blockDim.x + threadIdx.x;
    long long node = idx >> 2;
    if (node >= NN) return;
    int l4 = (int)(idx & 3);

    int beg = g_start[node];
    int end = g_start[node + 1];
    float acc = 0.f;
    for (int e = beg + l4; e < end; e += 4)
        acc += g_h2[__ldg(&g_csr[e])];
    acc += __shfl_down_sync(0xffffffffu, acc, 2, 4);
    acc += __shfl_down_sync(0xffffffffu, acc, 1, 4);
    if (l4 == 0) {
        float di = g_dinv[node];
        float v = (acc + g_h2[node]) * di + b2[0];
        out[node] = 1.0f / (1.0f + expf(-v));
    }
}

extern "C" void kernel_launch(void* const* d_in, const int* in_sizes, int n_in,
                              void* d_out, int out_size) {
    const float* x  = (const float*)d_in[0];
    const void*  ei = d_in[1];
    const float* W1 = (const float*)d_in[2];
    const float* b1 = (const float*)d_in[3];
    const float* W2 = (const float*)d_in[4];
    const float* b2 = (const float*)d_in[5];
    float* out = (float*)d_out;

    void* p_degi;
    cudaGetSymbolAddress(&p_degi, g_degi);
    cudaMemsetAsync(p_degi, 0, (size_t)NN * sizeof(int));

    detect_kernel<<<1, 256>>>(ei);
    degree_kernel<<<(EE + 255) / 256, 256>>>(ei);

    scan1_kernel<<<NBLK, SCAN_B>>>();
    scan2_kernel<<<1, 128>>>();
    scan3_kernel<<<(NN + 255) / 256, 256>>>();

    scatter_kernel<<<(EE + 255) / 256, 256>>>(ei);

    gemm1_kernel<<<(NN + 63) / 64, 256>>>(x, W1);

    long long t1 = (long long)NN * 4;
    agg1_fused_kernel<<<(unsigned)((t1 + 255) / 256), 256>>>(b1, W2);

    long long t2 = (long long)NN * 4;
    agg2_final_kernel<<<(unsigned)((t2 + 255) / 256), 256>>>(b2, out);
}

// round 7
// speedup vs baseline: 1.3061x; 1.3061x over previous
#include <cuda_runtime.h>
#include <math.h>

#define NN   100000
#define EE   3200000
#define INC  128
#define HIDC 16
#define SCAN_B 1024
#define NBLK ((NN + SCAN_B - 1) / SCAN_B)   // 98

// ---------------- scratch ----------------
__device__ int   g_degi[NN];
__device__ float g_dinv[NN];
__device__ int   g_start[NN + 1];
__device__ int   g_cur[NN];
__device__ int   g_bsum[128];
__device__ int   g_csr[EE];                  // src only (features pre-scaled)
__device__ float g_h1[(long long)NN * HIDC]; // h1 * dinv[node]
__device__ float g_h2[NN];                   // h2 * dinv[node]
__device__ int   g_is64;

// ---------------- edge dtype auto-detect ----------------
__global__ void detect_kernel(const void* ei) {
    __shared__ int bad;
    if (threadIdx.x == 0) bad = 0;
    __syncthreads();
    const long long* p = (const long long*)ei;
    long long v = p[threadIdx.x];
    if (v < 0 || v >= NN) bad = 1;
    __syncthreads();
    if (threadIdx.x == 0) g_is64 = bad ? 0 : 1;
}

// ---------------- degree (reads dst half only) ----------------
__global__ void degree_kernel(const void* ei) {
    long long e = (long long)blockIdx.x * blockDim.x + threadIdx.x;
    if (e >= EE) return;
    int d;
    if (g_is64) {
        const long long* p = (const long long*)ei;
        d = (int)p[(long long)EE + e];
    } else {
        const int* p = (const int*)ei;
        d = p[(long long)EE + e];
    }
    atomicAdd(&g_degi[d], 1);
}

// ---------------- prefix scan (dinv fused into scan1) ----------------
__global__ void scan1_kernel() {
    __shared__ int sh[SCAN_B];
    int t = threadIdx.x;
    int i = blockIdx.x * SCAN_B + t;
    int v = (i < NN) ? g_degi[i] : 0;
    if (i < NN) g_dinv[i] = rsqrtf((float)v + 1.0f);
    sh[t] = v;
#pragma unroll
    for (int off = 1; off < SCAN_B; off <<= 1) {
        __syncthreads();
        int add = (t >= off) ? sh[t - off] : 0;
        __syncthreads();
        sh[t] += add;
    }
    __syncthreads();
    if (i < NN) g_start[i] = sh[t] - v;
    if (t == SCAN_B - 1) g_bsum[blockIdx.x] = sh[t];
}

__global__ void scan2_kernel() {
    __shared__ int sh[128];
    int t = threadIdx.x;
    int v = (t < NBLK) ? g_bsum[t] : 0;
    sh[t] = v;
#pragma unroll
    for (int off = 1; off < 128; off <<= 1) {
        __syncthreads();
        int add = (t >= off) ? sh[t - off] : 0;
        __syncthreads();
        sh[t] += add;
    }
    __syncthreads();
    if (t < NBLK) g_bsum[t] = sh[t] - v;
}

__global__ void scan3_kernel() {
    int i = blockIdx.x * blockDim.x + threadIdx.x;
    if (i >= NN) return;
    int s = g_start[i] + g_bsum[i >> 10];
    g_start[i] = s;
    g_cur[i] = s;
    if (i == 0) g_start[NN] = EE;
}

// ---------------- scatter: CSR of src only (reads edge index directly) ----------------
__global__ void scatter_kernel(const void* ei) {
    long long e = (long long)blockIdx.x * blockDim.x + threadIdx.x;
    if (e >= EE) return;
    int s, d;
    if (g_is64) {
        const long long* p = (const long long*)ei;
        s = (int)p[e];
        d = (int)p[(long long)EE + e];
    } else {
        const int* p = (const int*)ei;
        s = p[e];
        d = p[(long long)EE + e];
    }
    int pos = atomicAdd(&g_cur[d], 1);
    g_csr[pos] = s;
}

// ---------------- h1 = (x @ W1) * dinv[node] ----------------
__global__ void __launch_bounds__(256) gemm1_kernel(const float* __restrict__ x,
                                                    const float* __restrict__ W1) {
    __shared__ float sW[INC * HIDC];
    __shared__ float sx[64 * 68];
    int t = threadIdx.x;
    long long base = (long long)blockIdx.x * 64;
    int local = t >> 2;
    int cg    = (t & 3) * 4;

    for (int i = t; i < INC * HIDC; i += 256) sW[i] = W1[i];

    float a0 = 0.f, a1 = 0.f, a2 = 0.f, a3 = 0.f;

#pragma unroll
    for (int kt = 0; kt < 2; kt++) {
        __syncthreads();
        const float4* x4 = (const float4*)x;
        for (int j = t; j < 1024; j += 256) {
            int r = j >> 4, c4 = j & 15;
            long long node = base + r;
            float4 v = (node < NN) ? x4[node * 32 + kt * 16 + c4]
                                   : make_float4(0.f, 0.f, 0.f, 0.f);
            *(float4*)&sx[r * 68 + c4 * 4] = v;
        }
        __syncthreads();
        const float* xr = &sx[local * 68];
        const float* wb = &sW[kt * 64 * HIDC + cg];
#pragma unroll 8
        for (int k = 0; k < 64; k++) {
            float xv = xr[k];
            float4 w = *(const float4*)(wb + k * HIDC);
            a0 = fmaf(xv, w.x, a0);
            a1 = fmaf(xv, w.y, a1);
            a2 = fmaf(xv, w.z, a2);
            a3 = fmaf(xv, w.w, a3);
        }
    }
    long long node = base + local;
    if (node < NN) {
        float di = g_dinv[node];
        *(float4*)&g_h1[node * HIDC + cg] =
            make_float4(a0 * di, a1 * di, a2 * di, a3 * di);
    }
}

// ---------------- layer-1 gather + self-loop + bias + relu + W2 dot ----------------
// 4 threads/node, 4 channels each; edge loop unrolled x4 (round-5 body).
__global__ void __launch_bounds__(256) agg1_fused_kernel(const float* __restrict__ b1,
                                                         const float* __restrict__ W2) {
    long long idx = (long long)blockIdx.x * blockDim.x + threadIdx.x;
    long long node = idx >> 2;
    if (node >= NN) return;
    int cg = (int)(idx & 3) * 4;

    int beg = g_start[node];
    int end = g_start[node + 1];
    float a0 = 0.f, a1 = 0.f, a2 = 0.f, a3 = 0.f;
    int e = beg;
    for (; e + 4 <= end; e += 4) {
        int s0 = __ldg(&g_csr[e]);
        int s1 = __ldg(&g_csr[e + 1]);
        int s2 = __ldg(&g_csr[e + 2]);
        int s3 = __ldg(&g_csr[e + 3]);
        float4 h0 = *(const float4*)&g_h1[(long long)s0 * HIDC + cg];
        float4 h1 = *(const float4*)&g_h1[(long long)s1 * HIDC + cg];
        float4 h2 = *(const float4*)&g_h1[(long long)s2 * HIDC + cg];
        float4 h3 = *(const float4*)&g_h1[(long long)s3 * HIDC + cg];
        a0 += h0.x + h1.x + h2.x + h3.x;
        a1 += h0.y + h1.y + h2.y + h3.y;
        a2 += h0.z + h1.z + h2.z + h3.z;
        a3 += h0.w + h1.w + h2.w + h3.w;
    }
    for (; e < end; e++) {
        int s = __ldg(&g_csr[e]);
        float4 h = *(const float4*)&g_h1[(long long)s * HIDC + cg];
        a0 += h.x; a1 += h.y; a2 += h.z; a3 += h.w;
    }
    float4 hs = *(const float4*)&g_h1[node * HIDC + cg];
    float di = g_dinv[node];
    float4 bb = *(const float4*)&b1[cg];
    float4 w2 = *(const float4*)&W2[cg];
    float v = fmaxf(fmaf(a0 + hs.x, di, bb.x), 0.f) * w2.x
            + fmaxf(fmaf(a1 + hs.y, di, bb.y), 0.f) * w2.y
            + fmaxf(fmaf(a2 + hs.z, di, bb.z), 0.f) * w2.z
            + fmaxf(fmaf(a3 + hs.w, di, bb.w), 0.f) * w2.w;
    v += __shfl_down_sync(0xffffffffu, v, 2, 4);
    v += __shfl_down_sync(0xffffffffu, v, 1, 4);
    if ((idx & 3) == 0) g_h2[node] = v * di;   // pre-scale for layer 2
}

// ---------------- layer-2 gather + self-loop + bias + sigmoid ----------------
__global__ void __launch_bounds__(256) agg2_final_kernel(const float* __restrict__ b2,
                                                         float* __restrict__ out) {
    long long idx = (long long)blockIdx.x * blockDim.x + threadIdx.x;
    long long node = idx >> 2;
    if (node >= NN) return;
    int l4 = (int)(idx & 3);

    int beg = g_start[node];
    int end = g_start[node + 1];
    float acc = 0.f;
    for (int e = beg + l4; e < end; e += 4)
        acc += g_h2[__ldg(&g_csr[e])];
    acc += __shfl_down_sync(0xffffffffu, acc, 2, 4);
    acc += __shfl_down_sync(0xffffffffu, acc, 1, 4);
    if (l4 == 0) {
        float di = g_dinv[node];
        float v = (acc + g_h2[node]) * di + b2[0];
        out[node] = 1.0f / (1.0f + expf(-v));
    }
}

extern "C" void kernel_launch(void* const* d_in, const int* in_sizes, int n_in,
                              void* d_out, int out_size) {
    const float* x  = (const float*)d_in[0];
    const void*  ei = d_in[1];
    const float* W1 = (const float*)d_in[2];
    const float* b1 = (const float*)d_in[3];
    const float* W2 = (const float*)d_in[4];
    const float* b2 = (const float*)d_in[5];
    float* out = (float*)d_out;

    void* p_degi;
    cudaGetSymbolAddress(&p_degi, g_degi);
    cudaMemsetAsync(p_degi, 0, (size_t)NN * sizeof(int));

    detect_kernel<<<1, 256>>>(ei);
    degree_kernel<<<(EE + 255) / 256, 256>>>(ei);

    scan1_kernel<<<NBLK, SCAN_B>>>();
    scan2_kernel<<<1, 128>>>();
    scan3_kernel<<<(NN + 255) / 256, 256>>>();

    scatter_kernel<<<(EE + 255) / 256, 256>>>(ei);

    gemm1_kernel<<<(NN + 63) / 64, 256>>>(x, W1);

    long long t1 = (long long)NN * 4;
    agg1_fused_kernel<<<(unsigned)((t1 + 255) / 256), 256>>>(b1, W2);

    long long t2 = (long long)NN * 4;
    agg2_final_kernel<<<(unsigned)((t2 + 255) / 256), 256>>>(b2, out);
}